// round 5
// baseline (speedup 1.0000x reference)
#include <cuda_runtime.h>
#include <cuda_bf16.h>
#include <cstdint>

// Problem constants
#define B_    64
#define TK_   2048
#define KD_   512
#define U_    1024
#define H_    8
#define D_    128
#define TT_   128          // t rows per block tile
#define KC_   64           // k chunk streamed per cp.async stage
#define KPAD_ 520          // key smem row pitch (bf16 elems), pad for bank spread
#define WKPAD_ 72          // wk smem row pitch (bf16 elems)

// Scratch (static __device__ arrays; no allocation)
__device__ float          g_qb[B_ * U_];        // q proj + bq + bk
__device__ __nv_bfloat16  g_wkb[U_ * KD_];      // Wk in bf16

// Shared memory layout (bytes)
#define SM_KEYS   0
#define SM_WKS    133120                        // 128*520*2
#define SM_QB     169984                        // + 2*128*72*2
#define SM_NV     174080                        // + 1024*4
#define SM_ADD    174592                        // + 128*4
#define SM_TMP    178688                        // + 8*128*4
#define SM_TOTAL  178704

// ---------------------------------------------------------------------------
__global__ void zero_kernel(float* __restrict__ out) {
    int idx = blockIdx.x * blockDim.x + threadIdx.x;
    if (idx < B_ * H_ * KD_) out[idx] = 0.0f;
}

// ---------------------------------------------------------------------------
// q[b,u] = query[b,:]·Wq[u,:] + bq[u] + bk[u]   (bk folded in: tanh(ks+qs))
__global__ void qproj_kernel(const float* __restrict__ query,
                             const float* __restrict__ Wq,
                             const float* __restrict__ bq,
                             const float* __restrict__ bk) {
    int b = blockIdx.x;
    int tid = threadIdx.x, lane = tid & 31, w = tid >> 5;
    __shared__ float qs[KD_];
    for (int i = tid; i < KD_; i += 256) qs[i] = query[b * KD_ + i];
    __syncthreads();
    for (int it = 0; it < U_ / 8; ++it) {
        int u = it * 8 + w;
        const float* wr = Wq + (size_t)u * KD_;
        float p = 0.f;
        #pragma unroll 4
        for (int k = lane; k < KD_; k += 32) p += qs[k] * wr[k];
        p += __shfl_xor_sync(~0u, p, 16);
        p += __shfl_xor_sync(~0u, p, 8);
        p += __shfl_xor_sync(~0u, p, 4);
        p += __shfl_xor_sync(~0u, p, 2);
        p += __shfl_xor_sync(~0u, p, 1);
        if (lane == 0) g_qb[b * U_ + u] = p + bq[u] + bk[u];
    }
}

// ---------------------------------------------------------------------------
__global__ void wkconv_kernel(const float* __restrict__ Wk) {
    int idx = blockIdx.x * blockDim.x + threadIdx.x;
    if (idx < U_ * KD_) g_wkb[idx] = __float2bfloat16(Wk[idx]);
}

// ---------------------------------------------------------------------------
__device__ __forceinline__ float tanh_fast(float x) {
    float y;
    asm("tanh.approx.f32 %0, %1;" : "=f"(y) : "f"(x));
    return y;
}

__global__ void __launch_bounds__(256, 1)
main_kernel(const float* __restrict__ key,
            const float* __restrict__ v,
            float* __restrict__ out) {
    extern __shared__ char smem[];
    __nv_bfloat16* keys = (__nv_bfloat16*)(smem + SM_KEYS);   // [128][520]
    __nv_bfloat16* wks  = (__nv_bfloat16*)(smem + SM_WKS);    // [2][128][72]
    float* qb_s  = (float*)(smem + SM_QB);                    // [1024]
    float* nv_s  = (float*)(smem + SM_NV);                    // [128]
    float* add_s = (float*)(smem + SM_ADD);                   // [8][128]
    float* tmp_s = (float*)(smem + SM_TMP);

    int bid = blockIdx.x;
    int b = bid >> 4, tt = bid & 15;
    int tid = threadIdx.x, lane = tid & 31, w = tid >> 5;
    int wm = w & 3, wn = w >> 2;   // 4 warps on M (32 rows each), 2 on N (64 cols each)

    const float* keyg = key + ((size_t)(b * TK_ + tt * TT_)) * KD_;

    // ---- init phase ----
    // key tile fp32 -> bf16 smem
    {
        const float4* kg4 = (const float4*)keyg;
        for (int i = tid; i < TT_ * KD_ / 4; i += 256) {
            int row = i >> 7, c4 = i & 127;
            float4 f = kg4[row * 128 + c4];
            __nv_bfloat162* dst = (__nv_bfloat162*)(keys + row * KPAD_ + c4 * 4);
            dst[0] = __floats2bfloat162_rn(f.x, f.y);
            dst[1] = __floats2bfloat162_rn(f.z, f.w);
        }
    }
    // q slice
    for (int i = tid; i < U_; i += 256) qb_s[i] = g_qb[b * U_ + i];
    // zero score buffer
    for (int i = tid; i < H_ * TT_; i += 256) add_s[i] = 0.f;
    // ||v|| (warp 0)
    if (w == 0) {
        float p = 0.f;
        #pragma unroll
        for (int j = 0; j < 4; ++j) { float x = v[lane + 32 * j]; p += x * x; }
        p += __shfl_xor_sync(~0u, p, 16);
        p += __shfl_xor_sync(~0u, p, 8);
        p += __shfl_xor_sync(~0u, p, 4);
        p += __shfl_xor_sync(~0u, p, 2);
        p += __shfl_xor_sync(~0u, p, 1);
        if (lane == 0) tmp_s[0] = rsqrtf(p) * 0.08838834764831845f;  // 1/sqrt(128)
    }
    __syncthreads();
    if (tid < D_) nv_s[tid] = v[tid] * tmp_s[0];

    // ---- wk chunk prefetch (cp.async) ----
    // chunk c: head = c>>3, kc = c&7; 128 rows x 64 bf16 (128B/row)
    auto prefetch = [&](int c) {
        int h = c >> 3, kc = c & 7, s = c & 1;
        int r = tid >> 1;
        const __nv_bfloat16* gsrc = g_wkb + (size_t)(h * D_ + r) * KD_ + kc * KC_ + (tid & 1) * 32;
        unsigned saddr = (unsigned)__cvta_generic_to_shared(
            wks + s * (D_ * WKPAD_) + r * WKPAD_ + (tid & 1) * 32);
        #pragma unroll
        for (int j = 0; j < 4; ++j)
            asm volatile("cp.async.cg.shared.global [%0], [%1], 16;\n"
                         :: "r"(saddr + j * 16), "l"(gsrc + j * 8));
        asm volatile("cp.async.commit_group;\n");
    };

    float c_[2][8][4];
    #pragma unroll
    for (int mt = 0; mt < 2; ++mt)
        #pragma unroll
        for (int nt = 0; nt < 8; ++nt)
            #pragma unroll
            for (int e = 0; e < 4; ++e) c_[mt][nt][e] = 0.f;

    prefetch(0);

    for (int c = 0; c < 64; ++c) {
        if (c < 63) {
            prefetch(c + 1);
            asm volatile("cp.async.wait_group 1;\n");
        } else {
            asm volatile("cp.async.wait_group 0;\n");
        }
        __syncthreads();

        const __nv_bfloat16* wkbuf = wks + (c & 1) * (D_ * WKPAD_);
        int kbase = (c & 7) * KC_;

        #pragma unroll
        for (int ks = 0; ks < 4; ++ks) {
            int kk = kbase + ks * 16;
            uint32_t a[2][4], bb[8][2];
            #pragma unroll
            for (int mt = 0; mt < 2; ++mt) {
                int m = wm * 32 + mt * 16 + (lane >> 2);
                const __nv_bfloat16* p = keys + m * KPAD_ + kk + (lane & 3) * 2;
                a[mt][0] = *(const uint32_t*)p;
                a[mt][1] = *(const uint32_t*)(p + 8 * KPAD_);
                a[mt][2] = *(const uint32_t*)(p + 8);
                a[mt][3] = *(const uint32_t*)(p + 8 * KPAD_ + 8);
            }
            #pragma unroll
            for (int nt = 0; nt < 8; ++nt) {
                int u = wn * 64 + nt * 8 + (lane >> 2);
                const __nv_bfloat16* p = wkbuf + u * WKPAD_ + ks * 16 + (lane & 3) * 2;
                bb[nt][0] = *(const uint32_t*)p;
                bb[nt][1] = *(const uint32_t*)(p + 8);
            }
            #pragma unroll
            for (int mt = 0; mt < 2; ++mt)
                #pragma unroll
                for (int nt = 0; nt < 8; ++nt)
                    asm volatile(
                        "mma.sync.aligned.m16n8k16.row.col.f32.bf16.bf16.f32 "
                        "{%0,%1,%2,%3}, {%4,%5,%6,%7}, {%8,%9}, {%0,%1,%2,%3};\n"
                        : "+f"(c_[mt][nt][0]), "+f"(c_[mt][nt][1]),
                          "+f"(c_[mt][nt][2]), "+f"(c_[mt][nt][3])
                        : "r"(a[mt][0]), "r"(a[mt][1]), "r"(a[mt][2]), "r"(a[mt][3]),
                          "r"(bb[nt][0]), "r"(bb[nt][1]));
        }

        if ((c & 7) == 7) {
            // epilogue: add_s[h][t] += sum_d nv[d] * tanh(kp + q)
            int h = c >> 3;
            const float* qh = qb_s + h * D_;
            #pragma unroll
            for (int mt = 0; mt < 2; ++mt) {
                float slo = 0.f, shi = 0.f;
                #pragma unroll
                for (int nt = 0; nt < 8; ++nt) {
                    int u0 = wn * 64 + nt * 8 + (lane & 3) * 2;
                    float q0 = qh[u0], q1 = qh[u0 + 1];
                    float n0 = nv_s[u0], n1 = nv_s[u0 + 1];
                    slo += n0 * tanh_fast(c_[mt][nt][0] + q0)
                         + n1 * tanh_fast(c_[mt][nt][1] + q1);
                    shi += n0 * tanh_fast(c_[mt][nt][2] + q0)
                         + n1 * tanh_fast(c_[mt][nt][3] + q1);
                    c_[mt][nt][0] = 0.f; c_[mt][nt][1] = 0.f;
                    c_[mt][nt][2] = 0.f; c_[mt][nt][3] = 0.f;
                }
                slo += __shfl_xor_sync(~0u, slo, 1);
                slo += __shfl_xor_sync(~0u, slo, 2);
                shi += __shfl_xor_sync(~0u, shi, 1);
                shi += __shfl_xor_sync(~0u, shi, 2);
                if ((lane & 3) == 0) {
                    int r = wm * 32 + mt * 16 + (lane >> 2);
                    atomicAdd(&add_s[h * TT_ + r], slo);
                    atomicAdd(&add_s[h * TT_ + r + 8], shi);
                }
            }
        }
        __syncthreads();
    }

    // ---- softmax over heads (legacy dim=1) ----
    if (tid < TT_) {
        float av[H_];
        float m = -1e30f;
        #pragma unroll
        for (int h = 0; h < H_; ++h) { av[h] = add_s[h * TT_ + tid]; m = fmaxf(m, av[h]); }
        float s = 0.f;
        #pragma unroll
        for (int h = 0; h < H_; ++h) { av[h] = __expf(av[h] - m); s += av[h]; }
        float inv = __fdividef(1.0f, s);
        #pragma unroll
        for (int h = 0; h < H_; ++h) add_s[h * TT_ + tid] = av[h] * inv;
    }
    __syncthreads();

    // ---- context: out[b,h,d] += sum_t w[h,t] * key[t,d]  (fp32 key from L2) ----
    {
        float acc[H_][2];
        #pragma unroll
        for (int h = 0; h < H_; ++h) { acc[h][0] = 0.f; acc[h][1] = 0.f; }
        const float2* kg2 = (const float2*)keyg;
        for (int t = 0; t < TT_; ++t) {
            float2 kv = kg2[t * (KD_ / 2) + tid];
            #pragma unroll
            for (int h = 0; h < H_; ++h) {
                float wv = add_s[h * TT_ + t];
                acc[h][0] += wv * kv.x;
                acc[h][1] += wv * kv.y;
            }
        }
        float* ob = out + (size_t)b * (H_ * KD_) + tid * 2;
        #pragma unroll
        for (int h = 0; h < H_; ++h) {
            atomicAdd(&ob[h * KD_], acc[h][0]);
            atomicAdd(&ob[h * KD_ + 1], acc[h][1]);
        }
    }
}

// ---------------------------------------------------------------------------
extern "C" void kernel_launch(void* const* d_in, const int* in_sizes, int n_in,
                              void* d_out, int out_size) {
    const float* query = (const float*)d_in[0];
    const float* key   = (const float*)d_in[1];
    const float* Wq    = (const float*)d_in[2];
    const float* bq    = (const float*)d_in[3];
    const float* Wk    = (const float*)d_in[4];
    const float* bk    = (const float*)d_in[5];
    const float* v     = (const float*)d_in[6];
    float* out = (float*)d_out;

    zero_kernel<<<(B_ * H_ * KD_ + 255) / 256, 256>>>(out);
    qproj_kernel<<<B_, 256>>>(query, Wq, bq, bk);
    wkconv_kernel<<<(U_ * KD_ + 255) / 256, 256>>>(Wk);

    cudaFuncSetAttribute(main_kernel,
                         cudaFuncAttributeMaxDynamicSharedMemorySize, SM_TOTAL);
    main_kernel<<<B_ * (TK_ / TT_), 256, SM_TOTAL>>>(key, v, out);
}

// round 8
// speedup vs baseline: 1.5018x; 1.5018x over previous
#include <cuda_runtime.h>
#include <cuda_bf16.h>
#include <cstdint>

// Problem constants
#define B_    64
#define TK_   2048
#define KD_   512
#define U_    1024
#define H_    8
#define D_    128
#define TT_   128          // t rows per block tile
#define KPAD_ 520          // key smem row pitch (bf16): 1040B = 65*16B, 260 words %32 = 4
#define WKPAD_ 72          // wk  smem row pitch (bf16): 144B = 9*16B, 36 words %32 = 4
#define WKSTG_ 18432       // one wk stage: 128 rows * 144B
#define NSTG_  4

// Scratch (static __device__ arrays; no allocation)
__device__ float          g_qb[B_ * U_];        // q proj + bq + bk
__device__ __nv_bfloat16  g_wkb[U_ * KD_];      // Wk in bf16

// Shared memory layout (bytes)
#define SM_KEYS   0                              // 128*520*2      = 133120
#define SM_WK     133120                         // 4*18432        = 73728
#define SM_QB     206848                         // 1024 f32
#define SM_NV     210944                         // 128 f32
#define SM_ADD    211456                         // 8*128 f32
#define SM_TMP    215552                         // 16 B
#define SM_TOTAL  215568

// ---------------------------------------------------------------------------
__device__ __forceinline__ uint32_t smem_u32(const void* p) {
    uint32_t a;
    asm("{ .reg .u64 t; cvta.to.shared.u64 t, %1; cvt.u32.u64 %0, t; }" : "=r"(a) : "l"(p));
    return a;
}
__device__ __forceinline__ float tanh_fast(float x) {
    float y;
    asm("tanh.approx.f32 %0, %1;" : "=f"(y) : "f"(x));
    return y;
}
#define LDSM4(r0, r1, r2, r3, addr) \
    asm volatile("ldmatrix.sync.aligned.m8n8.x4.shared.b16 {%0,%1,%2,%3}, [%4];" \
                 : "=r"(r0), "=r"(r1), "=r"(r2), "=r"(r3) : "r"(addr))

// ---------------------------------------------------------------------------
__global__ void zero_kernel(float* __restrict__ out) {
    int idx = blockIdx.x * blockDim.x + threadIdx.x;
    if (idx < B_ * H_ * KD_) out[idx] = 0.0f;
}

// q[b,u] = query[b,:].Wq[u,:] + bq[u] + bk[u] ; grid 512 = (b, oct of 128 u)
__global__ void qproj_kernel(const float* __restrict__ query,
                             const float* __restrict__ Wq,
                             const float* __restrict__ bq,
                             const float* __restrict__ bk) {
    int b = blockIdx.x >> 3, oct = blockIdx.x & 7;
    int tid = threadIdx.x, lane = tid & 31, w = tid >> 5;
    __shared__ float qs[KD_];
    for (int i = tid; i < KD_; i += 256) qs[i] = query[b * KD_ + i];
    __syncthreads();
    for (int it = 0; it < 16; ++it) {
        int u = oct * 128 + it * 8 + w;
        const float* wr = Wq + (size_t)u * KD_;
        float p = 0.f;
        #pragma unroll 4
        for (int k = lane; k < KD_; k += 32) p += qs[k] * wr[k];
        p += __shfl_xor_sync(~0u, p, 16);
        p += __shfl_xor_sync(~0u, p, 8);
        p += __shfl_xor_sync(~0u, p, 4);
        p += __shfl_xor_sync(~0u, p, 2);
        p += __shfl_xor_sync(~0u, p, 1);
        if (lane == 0) g_qb[b * U_ + u] = p + bq[u] + bk[u];
    }
}

__global__ void wkconv_kernel(const float* __restrict__ Wk) {
    int idx = blockIdx.x * blockDim.x + threadIdx.x;
    if (idx < U_ * KD_) g_wkb[idx] = __float2bfloat16(Wk[idx]);
}

// ---------------------------------------------------------------------------
__global__ void __launch_bounds__(256, 1)
main_kernel(const float* __restrict__ key,
            const float* __restrict__ v,
            float* __restrict__ out) {
    extern __shared__ char smem[];
    const uint32_t smb = smem_u32(smem);
    __nv_bfloat16* keys = (__nv_bfloat16*)(smem + SM_KEYS);
    float* qb_s  = (float*)(smem + SM_QB);
    float* nv_s  = (float*)(smem + SM_NV);
    float* add_s = (float*)(smem + SM_ADD);
    float* tmp_s = (float*)(smem + SM_TMP);

    int bid = blockIdx.x;
    int b = bid >> 4, tt = bid & 15;
    int tid = threadIdx.x, lane = tid & 31, w = tid >> 5;
    int wm = w & 3, wn = w >> 2;   // 4 warps on M (32 rows), 2 on N (64 cols)

    const float* keyg = key + ((size_t)(b * TK_ + tt * TT_)) * KD_;

    // ---- init phase ----
    {   // key tile fp32 -> bf16 smem (pitch KPAD_)
        const float4* kg4 = (const float4*)keyg;
        for (int i = tid; i < TT_ * KD_ / 4; i += 256) {
            int row = i >> 7, c4 = i & 127;
            float4 f = kg4[row * 128 + c4];
            __nv_bfloat162* dst = (__nv_bfloat162*)(keys + row * KPAD_ + c4 * 4);
            dst[0] = __floats2bfloat162_rn(f.x, f.y);
            dst[1] = __floats2bfloat162_rn(f.z, f.w);
        }
    }
    for (int i = tid; i < U_; i += 256) qb_s[i] = g_qb[b * U_ + i];
    for (int i = tid; i < H_ * TT_; i += 256) add_s[i] = 0.f;
    if (w == 0) {
        float p = 0.f;
        #pragma unroll
        for (int j = 0; j < 4; ++j) { float x = v[lane + 32 * j]; p += x * x; }
        p += __shfl_xor_sync(~0u, p, 16);
        p += __shfl_xor_sync(~0u, p, 8);
        p += __shfl_xor_sync(~0u, p, 4);
        p += __shfl_xor_sync(~0u, p, 2);
        p += __shfl_xor_sync(~0u, p, 1);
        if (lane == 0) tmp_s[0] = rsqrtf(p) * 0.08838834764831845f;  // 1/sqrt(128)
    }
    __syncthreads();
    if (tid < D_) nv_s[tid] = v[tid] * tmp_s[0];

    // ---- wk chunk prefetch: chunk c -> head c>>3, k-range (c&7)*64; stage c&3
    // 128 rows x 128B per chunk = 1024 x 16B; 256 threads x 4 transfers.
    auto prefetch = [&](int c) {
        if (c < 64) {
            int h = c >> 3, kc = c & 7;
            const __nv_bfloat16* src = g_wkb + (size_t)h * D_ * KD_ + kc * 64;
            uint32_t dst0 = smb + SM_WK + (c & 3) * WKSTG_;
            #pragma unroll
            for (int j = 0; j < 4; ++j) {
                int i = tid + j * 256;
                int r = i >> 3, g = i & 7;
                const void* gp = src + (size_t)r * KD_ + g * 8;
                asm volatile("cp.async.cg.shared.global [%0], [%1], 16;"
                             :: "r"(dst0 + r * (WKPAD_ * 2) + g * 16), "l"(gp));
            }
        }
        asm volatile("cp.async.commit_group;");
    };

    // per-thread ldmatrix base addresses
    // A (keys): lane l -> row wm*32 + mt*16 + (l&15), col k + (l>>4)*8
    uint32_t a_base = smb + SM_KEYS
                    + (uint32_t)(wm * 32 + (lane & 15)) * (KPAD_ * 2)
                    + (uint32_t)(lane >> 4) * 16;
    // B (wk): lane l -> row wn*64 + p*16 + (l&7) + ((l>>4)&1)*8, col k + ((l>>3)&1)*8
    uint32_t b_base = smb + SM_WK
                    + (uint32_t)(wn * 64 + (lane & 7) + ((lane >> 4) & 1) * 8) * (WKPAD_ * 2)
                    + (uint32_t)((lane >> 3) & 1) * 16;

    float c_[2][8][4];
    #pragma unroll
    for (int mt = 0; mt < 2; ++mt)
        #pragma unroll
        for (int nt = 0; nt < 8; ++nt)
            #pragma unroll
            for (int e = 0; e < 4; ++e) c_[mt][nt][e] = 0.f;

    prefetch(0); prefetch(1); prefetch(2);

    for (int c = 0; c < 64; ++c) {
        asm volatile("cp.async.wait_group 2;");
        __syncthreads();
        prefetch(c + 3);

        uint32_t bst = b_base + (c & 3) * WKSTG_;
        int kbase = (c & 7) * 64;

        #pragma unroll
        for (int ks = 0; ks < 4; ++ks) {
            uint32_t a[2][4], bb[4][4];
            uint32_t ao = a_base + (uint32_t)(kbase + ks * 16) * 2;
            LDSM4(a[0][0], a[0][1], a[0][2], a[0][3], ao);
            LDSM4(a[1][0], a[1][1], a[1][2], a[1][3], ao + 16 * (KPAD_ * 2));
            uint32_t bo = bst + (uint32_t)(ks * 16) * 2;
            #pragma unroll
            for (int p = 0; p < 4; ++p)
                LDSM4(bb[p][0], bb[p][1], bb[p][2], bb[p][3],
                      bo + (uint32_t)(p * 16) * (WKPAD_ * 2));
            #pragma unroll
            for (int mt = 0; mt < 2; ++mt)
                #pragma unroll
                for (int nt = 0; nt < 8; ++nt) {
                    uint32_t b0 = (nt & 1) ? bb[nt >> 1][2] : bb[nt >> 1][0];
                    uint32_t b1 = (nt & 1) ? bb[nt >> 1][3] : bb[nt >> 1][1];
                    asm volatile(
                        "mma.sync.aligned.m16n8k16.row.col.f32.bf16.bf16.f32 "
                        "{%0,%1,%2,%3}, {%4,%5,%6,%7}, {%8,%9}, {%0,%1,%2,%3};\n"
                        : "+f"(c_[mt][nt][0]), "+f"(c_[mt][nt][1]),
                          "+f"(c_[mt][nt][2]), "+f"(c_[mt][nt][3])
                        : "r"(a[mt][0]), "r"(a[mt][1]), "r"(a[mt][2]), "r"(a[mt][3]),
                          "r"(b0), "r"(b1));
                }
        }

        if ((c & 7) == 7) {
            // epilogue: add_s[h][t] += sum_u nv[u] * tanh(kp + q)
            int h = c >> 3;
            const float* qh = qb_s + h * D_;
            #pragma unroll
            for (int mt = 0; mt < 2; ++mt) {
                float slo = 0.f, shi = 0.f;
                #pragma unroll
                for (int nt = 0; nt < 8; ++nt) {
                    int u0 = wn * 64 + nt * 8 + (lane & 3) * 2;
                    float q0 = qh[u0], q1 = qh[u0 + 1];
                    float n0 = nv_s[u0], n1 = nv_s[u0 + 1];
                    slo += n0 * tanh_fast(c_[mt][nt][0] + q0)
                         + n1 * tanh_fast(c_[mt][nt][1] + q1);
                    shi += n0 * tanh_fast(c_[mt][nt][2] + q0)
                         + n1 * tanh_fast(c_[mt][nt][3] + q1);
                    c_[mt][nt][0] = 0.f; c_[mt][nt][1] = 0.f;
                    c_[mt][nt][2] = 0.f; c_[mt][nt][3] = 0.f;
                }
                slo += __shfl_xor_sync(~0u, slo, 1);
                slo += __shfl_xor_sync(~0u, slo, 2);
                shi += __shfl_xor_sync(~0u, shi, 1);
                shi += __shfl_xor_sync(~0u, shi, 2);
                if ((lane & 3) == 0) {
                    int r = wm * 32 + mt * 16 + (lane >> 2);
                    atomicAdd(&add_s[h * TT_ + r], slo);
                    atomicAdd(&add_s[h * TT_ + r + 8], shi);
                }
            }
        }
    }
    __syncthreads();

    // ---- softmax over heads (legacy dim=1) ----
    if (tid < TT_) {
        float av[H_];
        float m = -1e30f;
        #pragma unroll
        for (int h = 0; h < H_; ++h) { av[h] = add_s[h * TT_ + tid]; m = fmaxf(m, av[h]); }
        float s = 0.f;
        #pragma unroll
        for (int h = 0; h < H_; ++h) { av[h] = __expf(av[h] - m); s += av[h]; }
        float inv = __fdividef(1.0f, s);
        #pragma unroll
        for (int h = 0; h < H_; ++h) add_s[h * TT_ + tid] = av[h] * inv;
    }
    __syncthreads();

    // ---- context: out[b,h,d] += sum_t w[h,t] * key[t,d] (fp32 key from L2) ----
    {
        float acc[H_][2];
        #pragma unroll
        for (int h = 0; h < H_; ++h) { acc[h][0] = 0.f; acc[h][1] = 0.f; }
        const float2* kg2 = (const float2*)keyg;
        for (int t = 0; t < TT_; ++t) {
            float2 kv = kg2[t * (KD_ / 2) + tid];
            #pragma unroll
            for (int h = 0; h < H_; ++h) {
                float wv = add_s[h * TT_ + t];
                acc[h][0] += wv * kv.x;
                acc[h][1] += wv * kv.y;
            }
        }
        float* ob = out + (size_t)b * (H_ * KD_) + tid * 2;
        #pragma unroll
        for (int h = 0; h < H_; ++h) {
            atomicAdd(&ob[h * KD_], acc[h][0]);
            atomicAdd(&ob[h * KD_ + 1], acc[h][1]);
        }
    }
}

// ---------------------------------------------------------------------------
extern "C" void kernel_launch(void* const* d_in, const int* in_sizes, int n_in,
                              void* d_out, int out_size) {
    const float* query = (const float*)d_in[0];
    const float* key   = (const float*)d_in[1];
    const float* Wq    = (const float*)d_in[2];
    const float* bq    = (const float*)d_in[3];
    const float* Wk    = (const float*)d_in[4];
    const float* bk    = (const float*)d_in[5];
    const float* v     = (const float*)d_in[6];
    float* out = (float*)d_out;

    zero_kernel<<<(B_ * H_ * KD_ + 255) / 256, 256>>>(out);
    qproj_kernel<<<B_ * 8, 256>>>(query, Wq, bq, bk);
    wkconv_kernel<<<(U_ * KD_ + 255) / 256, 256>>>(Wk);

    cudaFuncSetAttribute(main_kernel,
                         cudaFuncAttributeMaxDynamicSharedMemorySize, SM_TOTAL);
    main_kernel<<<B_ * (TK_ / TT_), 256, SM_TOTAL>>>(key, v, out);
}